// round 11
// baseline (speedup 1.0000x reference)
#include <cuda_runtime.h>
#include <cuda_bf16.h>
#include <math.h>
#include <cstdint>

// Problem constants
#define NB     32
#define HQ     32
#define HKV    8
#define NREP   4
#define HD     128
#define DIM    4096
#define KVD    1024
#define MAXSEQ 4096
#define NEWPOS 4095

#define QKV_OUTS 6144
#define NSPLIT 16
#define SCHUNK 256

// mma GEMM config
#define TCKS   8        // k-split
#define KBLK   512      // K per block
#define NCHUNK 16       // chunks of 32 k per block
#define MBLK   256      // outs per block

// ---------------- scratch (device globals) ------------------------------------
__device__ float g_qkvp[TCKS * NB * QKV_OUTS];
__device__ float g_q   [NB * DIM];
__device__ float g_kn  [NB * KVD];
__device__ float g_vn  [NB * KVD];
__device__ float g_pm  [NB * HKV * NSPLIT * NREP];
__device__ float g_pl  [NB * HKV * NSPLIT * NREP];
__device__ float g_pacc[NB * HKV * NSPLIT * NREP * HD];
__device__ float g_xhi [NB * DIM];
__device__ float g_xlo [NB * DIM];
__device__ float g_ahi [NB * DIM];
__device__ float g_alo [NB * DIM];
__device__ float g_op  [TCKS * NB * DIM];

// ---------------- helpers -------------------------------------------------------
__device__ __forceinline__ unsigned long long f2fma(unsigned long long a,
                                                    unsigned long long b,
                                                    unsigned long long c) {
    unsigned long long d;
    asm("fma.rn.f32x2 %0, %1, %2, %3;" : "=l"(d) : "l"(a), "l"(b), "l"(c));
    return d;
}
__device__ __forceinline__ float2 uf2(unsigned long long u) {
    float2 f;
    asm("mov.b64 {%0, %1}, %2;" : "=f"(f.x), "=f"(f.y) : "l"(u));
    return f;
}
__device__ __forceinline__ unsigned long long dupf(float p) {
    unsigned long long u;
    asm("mov.b64 %0, {%1, %1};" : "=l"(u) : "f"(p));
    return u;
}
__device__ __forceinline__ unsigned long long pack2(float a, float b) {
    unsigned long long u;
    asm("mov.b64 %0, {%1, %2};" : "=l"(u) : "f"(a), "f"(b));
    return u;
}
__device__ __forceinline__ float tf32of(float v) {
    return __uint_as_float(__float_as_uint(v) & 0xFFFFE000u);
}

// m16n8k8 tf32 HMMA: D += A * B   (A 16x8 row, B 8x8 col, fp32 accum)
__device__ __forceinline__ void mma1688(float* d, const uint32_t* a, const uint32_t* b) {
    asm volatile(
        "mma.sync.aligned.m16n8k8.row.col.f32.tf32.tf32.f32 "
        "{%0,%1,%2,%3}, {%4,%5,%6,%7}, {%8,%9}, {%0,%1,%2,%3};"
        : "+f"(d[0]), "+f"(d[1]), "+f"(d[2]), "+f"(d[3])
        : "r"(a[0]), "r"(a[1]), "r"(a[2]), "r"(a[3]), "r"(b[0]), "r"(b[1]));
}

// ------------------------------------------------------------------------------
// split x into tf32-exact hi + fp32 lo
// ------------------------------------------------------------------------------
__global__ void split_tf32(const float* __restrict__ x,
                           float* __restrict__ xhi, float* __restrict__ xlo)
{
    const int i = blockIdx.x * 256 + threadIdx.x;   // < 131072
    const float v = x[i];
    const float h = tf32of(v);
    xhi[i] = h;
    xlo[i] = v - h;
}

// ------------------------------------------------------------------------------
// HMMA tf32 GEMM v3: yp[ks][b][o] = sum_{k in split} x[b,k] * W[o,k].
// 3-term exact-ish split: Wh*xh + Wh*xl + Wl*xh  (rel_err ~1e-5).
// Block tile 256 outs x 32 b x 512 K. 8 warps, warp = 2 mtiles x 4 ntiles.
// grid (OUTS/256, TCKS), 256 threads. Fragment-ordered double-buffered smem.
// W stored raw; hi/lo split recomputed in registers per k8 (A-frag reuse x4 nt).
// ------------------------------------------------------------------------------
__global__ __launch_bounds__(256)
void gemm_mma(const float* __restrict__ xhi, const float* __restrict__ xlo,
              const float* __restrict__ w0, const float* __restrict__ w1,
              const float* __restrict__ w2, int n0, int n1,
              float* __restrict__ yp, int OUTS)
{
    // fragment-ordered tiles
    __shared__ __align__(16) float Wf[2][4][16][4][32];     // 64KB (raw fp32 W)
    __shared__ __align__(16) float Xf[2][4][2][4][2][32];   // 16KB

    const int t = threadIdx.x;
    const int lane = t & 31;
    const int w = t >> 5;

    const int obase = blockIdx.x * MBLK;
    const float* wp;
    int orow;
    if (obase < n0)           { wp = w0; orow = obase; }
    else if (obase < n0 + n1) { wp = w1; orow = obase - n0; }
    else                      { wp = w2; orow = obase - n0 - n1; }
    const int kb = blockIdx.y * KBLK;

    // staging geometry: W 8 float4/thread (256 rows x 32 k), X 2 float4
    int wr_[8], wq_[8];
#pragma unroll
    for (int i = 0; i < 8; i++) { const int e = i * 256 + t; wr_[i] = e >> 3; wq_[i] = e & 7; }
    int xh_[2], xb_[2], xq_[2];
#pragma unroll
    for (int j = 0; j < 2; j++) {
        const int e = j * 256 + t;
        xh_[j] = e >> 8; xb_[j] = (e >> 3) & 31; xq_[j] = e & 7;
    }

    const int wm = w * 2;   // 2 M-tiles: wm, wm+1

    float d[2][4][4];
#pragma unroll
    for (int mi = 0; mi < 2; mi++)
#pragma unroll
        for (int nt = 0; nt < 4; nt++)
#pragma unroll
            for (int r = 0; r < 4; r++) d[mi][nt][r] = 0.f;

    // prologue: prefetch chunk 0
    float4 wreg[8], xreg[2];
#pragma unroll
    for (int i = 0; i < 8; i++)
        wreg[i] = *(const float4*)&wp[(size_t)(orow + wr_[i]) * 4096 + kb + wq_[i] * 4];
#pragma unroll
    for (int j = 0; j < 2; j++) {
        const float* src = xh_[j] ? xlo : xhi;
        xreg[j] = *(const float4*)&src[(size_t)xb_[j] * 4096 + kb + xq_[j] * 4];
    }

    for (int ch = 0; ch < NCHUNK; ch++) {
        const int buf = ch & 1;
        __syncthreads();   // readers of buf (compute ch-2) done
        // stage raw W + x hi/lo
#pragma unroll
        for (int i = 0; i < 8; i++) {
            const int r = wr_[i], qq = wq_[i];
            const int reg = (qq & 1) * 2 + (((r & 15) >= 8) ? 1 : 0);
            *(float4*)&Wf[buf][qq >> 1][r >> 4][reg][(r & 7) * 4] = wreg[i];
        }
#pragma unroll
        for (int j = 0; j < 2; j++) {
            *(float4*)&Xf[buf][xq_[j] >> 1][xh_[j]][xb_[j] >> 3][xq_[j] & 1][(xb_[j] & 7) * 4] = xreg[j];
        }
        __syncthreads();   // staged data visible

        // prefetch next chunk (overlaps compute)
        if (ch + 1 < NCHUNK) {
            const int kc = kb + (ch + 1) * 32;
#pragma unroll
            for (int i = 0; i < 8; i++)
                wreg[i] = *(const float4*)&wp[(size_t)(orow + wr_[i]) * 4096 + kc + wq_[i] * 4];
#pragma unroll
            for (int j = 0; j < 2; j++) {
                const float* src = xh_[j] ? xlo : xhi;
                xreg[j] = *(const float4*)&src[(size_t)xb_[j] * 4096 + kc + xq_[j] * 4];
            }
        }

#pragma unroll
        for (int k8 = 0; k8 < 4; k8++) {
            uint32_t ah[2][4], al[2][4];
#pragma unroll
            for (int mi = 0; mi < 2; mi++)
#pragma unroll
                for (int r = 0; r < 4; r++) {
                    const float av = Wf[buf][k8][wm + mi][r][lane];
                    const uint32_t hu = __float_as_uint(av) & 0xFFFFE000u;
                    ah[mi][r] = hu;
                    al[mi][r] = __float_as_uint(av - __uint_as_float(hu));
                }
            uint32_t bh[4][2], bl[4][2];
#pragma unroll
            for (int nt = 0; nt < 4; nt++) {
                bh[nt][0] = __float_as_uint(Xf[buf][k8][0][nt][0][lane]);
                bh[nt][1] = __float_as_uint(Xf[buf][k8][0][nt][1][lane]);
                bl[nt][0] = __float_as_uint(Xf[buf][k8][1][nt][0][lane]);
                bl[nt][1] = __float_as_uint(Xf[buf][k8][1][nt][1][lane]);
            }
#pragma unroll
            for (int mi = 0; mi < 2; mi++)
#pragma unroll
                for (int nt = 0; nt < 4; nt++) {
                    mma1688(d[mi][nt], ah[mi], bh[nt]);
                    mma1688(d[mi][nt], ah[mi], bl[nt]);
                    mma1688(d[mi][nt], al[mi], bh[nt]);
                }
        }
    }

    // output: D fragment -> yp[ks][b][o]
#pragma unroll
    for (int mi = 0; mi < 2; mi++)
#pragma unroll
        for (int nt = 0; nt < 4; nt++)
#pragma unroll
            for (int r = 0; r < 4; r++) {
                const int o = obase + (wm + mi) * 16 + (lane >> 2) + (r >> 1) * 8;
                const int b = nt * 8 + (lane & 3) * 2 + (r & 1);
                yp[(size_t)(blockIdx.y * NB + b) * OUTS + o] = d[mi][nt][r];
            }
}

// ------------------------------------------------------------------------------
// RoPE + 8-way k-split reduce. grid 384 x 256.
// ------------------------------------------------------------------------------
__global__ void rope_reduce(const float* __restrict__ qkvp,
                            const float* __restrict__ fc,
                            const float* __restrict__ fs,
                            float* __restrict__ qout,
                            float* __restrict__ kout,
                            float* __restrict__ vout)
{
    const int idx = blockIdx.x * 256 + threadIdx.x;
    const int b  = idx / 3072;
    const int jp = idx % 3072;
    const int j0 = jp * 2;

    float v0 = 0.f, v1 = 0.f;
#pragma unroll
    for (int s = 0; s < TCKS; s++) {
        const float* p = qkvp + (size_t)(s * NB + b) * QKV_OUTS + j0;
        v0 += p[0];
        v1 += p[1];
    }
    if (j0 < DIM + KVD) {
        const int i = jp & 63;
        const float c = fc[i], s_ = fs[i];
        const float re = v0 * c - v1 * s_;
        const float im = v0 * s_ + v1 * c;
        v0 = re; v1 = im;
    }
    if (j0 < DIM) {
        qout[b * DIM + j0] = v0;
        qout[b * DIM + j0 + 1] = v1;
    } else if (j0 < DIM + KVD) {
        kout[b * KVD + (j0 - DIM)] = v0;
        kout[b * KVD + (j0 - DIM) + 1] = v1;
    } else {
        vout[b * KVD + (j0 - DIM - KVD)] = v0;
        vout[b * KVD + (j0 - DIM - KVD) + 1] = v1;
    }
}

// ------------------------------------------------------------------------------
__global__ void dummy_k() {}

// ------------------------------------------------------------------------------
// Flash-decode split attention (unchanged, 82% DRAM). grid (256, 16), 256 thr.
// ------------------------------------------------------------------------------
__global__ __launch_bounds__(256, 4)
void attn_split(const float* __restrict__ q,
                const float* __restrict__ ck,
                const float* __restrict__ cv,
                float* __restrict__ pm,
                float* __restrict__ pl,
                float* __restrict__ pacc)
{
    const int bg = blockIdx.x;
    const int b = bg >> 3, g = bg & 7;
    const int split = blockIdx.y;
    const int t = threadIdx.x;
    const int lane = t & 31, w = t >> 5;
    const int sbase = split * SCHUNK;

    __shared__ __align__(16) float sm[11012];
    float* qs   = sm;
    float* kbuf = sm + 512;
    float* sc   = sm + 8960;
    float* part = sm + 9984;
    float* mf   = sm + 11008;
    float* pvp  = kbuf;

    const float scale = 0.08838834764831845f;

    for (int i = t; i < 512; i += 256) {
        const int r = i >> 7, d = i & 127;
        qs[r * 128 + d] = q[(b * HQ + g * NREP + r) * HD + d] * scale;
    }

    const int s_loc = t & 31;
    const int dg = t >> 5;
    const int base_d = dg * 16;
    const size_t ckb = (size_t)(b * MAXSEQ) * KVD + g * HD;

    float4 kreg[4];
#pragma unroll
    for (int i = 0; i < 4; i++) {
        const int f4 = t + i * 256;
        const int row = f4 >> 5, c4 = (f4 & 31) * 4;
        kreg[i] = __ldcs((const float4*)&ck[ckb + (size_t)(sbase + row) * KVD + c4]);
    }

    float mloc = -1e30f;

    for (int tile = 0; tile < SCHUNK / 32; tile++) {
        float* kb = kbuf + (tile & 1) * 4224;
#pragma unroll
        for (int i = 0; i < 4; i++) {
            const int f4 = t + i * 256;
            const int row = f4 >> 5, c4 = (f4 & 31) * 4;
            *(float4*)&kb[row * 132 + c4] = kreg[i];
        }
        __syncthreads();

        if (tile + 1 < SCHUNK / 32) {
#pragma unroll
            for (int i = 0; i < 4; i++) {
                const int f4 = t + i * 256;
                const int row = f4 >> 5, c4 = (f4 & 31) * 4;
                kreg[i] = __ldcs((const float4*)&ck[ckb + (size_t)(sbase + (tile + 1) * 32 + row) * KVD + c4]);
            }
        }

        unsigned long long racc[4] = {0ull, 0ull, 0ull, 0ull};
#pragma unroll
        for (int c = 0; c < 4; c++) {
            ulonglong2 kk = *(const ulonglong2*)&kb[s_loc * 132 + base_d + c * 4];
#pragma unroll
            for (int r = 0; r < 4; r++) {
                ulonglong2 qq = *(const ulonglong2*)&qs[r * 128 + base_d + c * 4];
                racc[r] = f2fma(kk.x, qq.x, racc[r]);
                racc[r] = f2fma(kk.y, qq.y, racc[r]);
            }
        }
#pragma unroll
        for (int r = 0; r < 4; r++) {
            float2 f = uf2(racc[r]);
            part[(dg * 4 + r) * 32 + s_loc] = f.x + f.y;
        }
        __syncthreads();
        if (t < 128) {
            const int r = t >> 5;
            float val = 0.f;
#pragma unroll
            for (int d8 = 0; d8 < 8; d8++) val += part[(d8 * 4 + r) * 32 + lane];
            const int sg = sbase + tile * 32 + lane;
            if (sg == NEWPOS) val = -1e30f;
            sc[r * SCHUNK + tile * 32 + lane] = val;
            mloc = fmaxf(mloc, val);
        }
    }

    if (t < 128) {
#pragma unroll
        for (int off = 16; off; off >>= 1)
            mloc = fmaxf(mloc, __shfl_xor_sync(0xffffffffu, mloc, off));
        if (lane == 0) mf[t >> 5] = mloc;
    }
    __syncthreads();

    {
        const int r = t >> 6, s0 = t & 63;
        const float m = mf[r];
        float ls = 0.f;
#pragma unroll
        for (int j = 0; j < SCHUNK / 64; j++) {
            const int sl = s0 + j * 64;
            const float p = __expf(sc[r * SCHUNK + sl] - m);
            sc[r * SCHUNK + sl] = p;
            ls += p;
        }
#pragma unroll
        for (int off = 16; off; off >>= 1)
            ls += __shfl_xor_sync(0xffffffffu, ls, off);
        if (lane == 0) part[w] = ls;
    }
    __syncthreads();
    if (t < 4) {
        pm[bg * (NSPLIT * NREP) + split * NREP + t] = mf[t];
        pl[bg * (NSPLIT * NREP) + split * NREP + t] = part[2 * t] + part[2 * t + 1];
    }

    {
        const int dq = lane;
        const int sg8 = w;
        const size_t cvb = (size_t)(b * MAXSEQ) * KVD + g * HD + dq * 4;
        unsigned long long a[4][2];
#pragma unroll
        for (int r = 0; r < 4; r++) { a[r][0] = 0ull; a[r][1] = 0ull; }
        for (int i0 = 0; i0 < 32; i0 += 4) {
            float4 vf[4];
#pragma unroll
            for (int j = 0; j < 4; j++) {
                const int sl = sg8 * 32 + i0 + j;
                vf[j] = __ldcs((const float4*)&cv[cvb + (size_t)(sbase + sl) * KVD]);
            }
#pragma unroll
            for (int j = 0; j < 4; j++) {
                const int sl = sg8 * 32 + i0 + j;
                const unsigned long long vx = pack2(vf[j].x, vf[j].y);
                const unsigned long long vy = pack2(vf[j].z, vf[j].w);
#pragma unroll
                for (int r = 0; r < 4; r++) {
                    const unsigned long long pp = dupf(sc[r * SCHUNK + sl]);
                    a[r][0] = f2fma(pp, vx, a[r][0]);
                    a[r][1] = f2fma(pp, vy, a[r][1]);
                }
            }
        }
#pragma unroll
        for (int r = 0; r < 4; r++) {
            float2 f0 = uf2(a[r][0]), f1 = uf2(a[r][1]);
            float4 o4 = make_float4(f0.x, f0.y, f1.x, f1.y);
            *(float4*)&pvp[(sg8 * 4 + r) * 128 + dq * 4] = o4;
        }
    }
    __syncthreads();
#pragma unroll
    for (int i = 0; i < 2; i++) {
        const int idx = t + i * 256;
        const int r = idx >> 7, d = idx & 127;
        float v = 0.f;
#pragma unroll
        for (int sgp = 0; sgp < 8; sgp++) v += pvp[(sgp * 4 + r) * 128 + d];
        pacc[((bg * NSPLIT + split) * NREP + r) * HD + d] = v;
    }
}

// ------------------------------------------------------------------------------
// Combine partials + new token; emit attn as tf32 hi/lo for the wo GEMM.
// grid (256, 4), 128 threads.
// ------------------------------------------------------------------------------
__global__ __launch_bounds__(128)
void attn_combine(const float* __restrict__ q,
                  const float* __restrict__ kn,
                  const float* __restrict__ vn,
                  const float* __restrict__ pm,
                  const float* __restrict__ pl,
                  const float* __restrict__ pacc,
                  float* __restrict__ ahi,
                  float* __restrict__ alo)
{
    const int bg = blockIdx.x;
    const int b = bg >> 3, g = bg & 7;
    const int rr = blockIdx.y;
    const int t = threadIdx.x, lane = t & 31;
    __shared__ float sn1;
    const float scale = 0.08838834764831845f;

    if (t < 32) {
        const float4 k4 = *(const float4*)&kn[(b * HKV + g) * HD + lane * 4];
        const float4 q4 = *(const float4*)&q[(b * HQ + g * NREP + rr) * HD + lane * 4];
        float ds = k4.x * q4.x + k4.y * q4.y + k4.z * q4.z + k4.w * q4.w;
#pragma unroll
        for (int off = 16; off; off >>= 1) ds += __shfl_xor_sync(0xffffffffu, ds, off);
        if (lane == 0) sn1 = ds * scale;
    }
    __syncthreads();

    const int d = t;
    const float vnew = vn[(b * HKV + g) * HD + d];

    float mi[NSPLIT];
    float M = sn1;
#pragma unroll
    for (int i = 0; i < NSPLIT; i++) {
        mi[i] = pm[bg * (NSPLIT * NREP) + i * NREP + rr];
        M = fmaxf(M, mi[i]);
    }
    const float en = __expf(sn1 - M);
    float L = en;
    float num = en * vnew;
#pragma unroll
    for (int i = 0; i < NSPLIT; i++) {
        const float e = __expf(mi[i] - M);
        L += pl[bg * (NSPLIT * NREP) + i * NREP + rr] * e;
        num += pacc[((bg * NSPLIT + i) * NREP + rr) * HD + d] * e;
    }
    const float v = num / L;
    const float h = tf32of(v);
    const int idx = (b * HQ + g * NREP + rr) * HD + d;
    ahi[idx] = h;
    alo[idx] = v - h;
}

// ------------------------------------------------------------------------------
// Final 8-way reduce of wo partials -> d_out. grid 512 x 256.
// ------------------------------------------------------------------------------
__global__ void final_reduce(const float* __restrict__ op, float* __restrict__ out)
{
    const int idx = blockIdx.x * 256 + threadIdx.x;
    float v = 0.f;
#pragma unroll
    for (int s = 0; s < TCKS; s++) v += op[(size_t)s * NB * DIM + idx];
    out[idx] = v;
}

// ------------------------------------------------------------------------------
extern "C" void kernel_launch(void* const* d_in, const int* in_sizes, int n_in,
                              void* d_out, int out_size)
{
    const float* x  = (const float*)d_in[0];
    const float* ck = (const float*)d_in[1];
    const float* cv = (const float*)d_in[2];
    const float* wq = (const float*)d_in[3];
    const float* wk = (const float*)d_in[4];
    const float* wv = (const float*)d_in[5];
    const float* wo = (const float*)d_in[6];
    const float* fc = (const float*)d_in[7];
    const float* fs = (const float*)d_in[8];
    float* out = (float*)d_out;

    float *qkvp, *qb, *kn, *vn, *pm, *pl, *pacc, *xhi, *xlo, *ahi, *alo, *op;
    cudaGetSymbolAddress((void**)&qkvp, g_qkvp);
    cudaGetSymbolAddress((void**)&qb,   g_q);
    cudaGetSymbolAddress((void**)&kn,   g_kn);
    cudaGetSymbolAddress((void**)&vn,   g_vn);
    cudaGetSymbolAddress((void**)&pm,   g_pm);
    cudaGetSymbolAddress((void**)&pl,   g_pl);
    cudaGetSymbolAddress((void**)&pacc, g_pacc);
    cudaGetSymbolAddress((void**)&xhi,  g_xhi);
    cudaGetSymbolAddress((void**)&xlo,  g_xlo);
    cudaGetSymbolAddress((void**)&ahi,  g_ahi);
    cudaGetSymbolAddress((void**)&alo,  g_alo);
    cudaGetSymbolAddress((void**)&op,   g_op);

    // 0) x -> tf32 hi/lo split
    split_tf32<<<512, 256>>>(x, xhi, xlo);
    // 1-2) dummies — put the qkv HMMA GEMM in the ncu capture slot (#3)
    dummy_k<<<1, 32>>>();
    dummy_k<<<1, 32>>>();
    // 3) QKV projection on tensor cores (HMMA tf32, 3-term, M=256 tiles)
    gemm_mma<<<dim3(QKV_OUTS / MBLK, TCKS), 256>>>(
        xhi, xlo, wq, wk, wv, DIM, KVD, qkvp, QKV_OUTS);
    // 4) 8-way reduce + RoPE
    rope_reduce<<<384, 256>>>(qkvp, fc, fs, qb, kn, vn);
    // 5) split attention over cached tokens (pos 4095 masked)
    attn_split<<<dim3(NB * HKV, NSPLIT), 256>>>(qb, ck, cv, pm, pl, pacc);
    // 6) combine + new token; emit hi/lo
    attn_combine<<<dim3(NB * HKV, NREP), 128>>>(qb, kn, vn, pm, pl, pacc, ahi, alo);
    // 7) output projection on tensor cores
    gemm_mma<<<dim3(DIM / MBLK, TCKS), 256>>>(
        ahi, alo, wo, wo, wo, DIM, 0, op, DIM);
    // 8) reduce to d_out
    final_reduce<<<512, 256>>>(op, out);
}

// round 12
// speedup vs baseline: 1.0293x; 1.0293x over previous
#include <cuda_runtime.h>
#include <cuda_bf16.h>
#include <math.h>

// Problem constants
#define NB     32      // batch
#define HQ     32
#define HKV    8
#define NREP   4
#define HD     128
#define DIM    4096    // HQ*HD
#define KVD    1024    // HKV*HD
#define MAXSEQ 4096
#define NEWPOS 4095

#define KSPLIT 32      // GEMM k-split
#define KB     128     // 4096 / KSPLIT
#define QKV_OUTS 6144  // 4096 + 1024 + 1024
#define NSPLIT 16      // attention seq splits
#define SCHUNK 256     // 4096 / 16

// ---------------- scratch (device globals; no allocations allowed) -------------
__device__ float g_qkvp[KSPLIT * NB * QKV_OUTS];   // qkv gemm partials
__device__ float g_q   [NB * DIM];                  // rope'd q
__device__ float g_kn  [NB * KVD];                  // rope'd new k
__device__ float g_vn  [NB * KVD];                  // new v
__device__ float g_pm  [NB * HKV * NSPLIT * NREP];  // partial max
__device__ float g_pl  [NB * HKV * NSPLIT * NREP];  // partial sum
__device__ float g_pacc[NB * HKV * NSPLIT * NREP * HD]; // partial acc
__device__ float g_attn[NB * DIM];                  // attention output
__device__ float g_op  [KSPLIT * NB * DIM];         // wo gemm partials

// ---------------- f32x2 helpers -------------------------------------------------
__device__ __forceinline__ unsigned long long f2fma(unsigned long long a,
                                                    unsigned long long b,
                                                    unsigned long long c) {
    unsigned long long d;
    asm("fma.rn.f32x2 %0, %1, %2, %3;" : "=l"(d) : "l"(a), "l"(b), "l"(c));
    return d;
}
__device__ __forceinline__ float2 uf2(unsigned long long u) {
    float2 f;
    asm("mov.b64 {%0, %1}, %2;" : "=f"(f.x), "=f"(f.y) : "l"(u));
    return f;
}
__device__ __forceinline__ unsigned long long dupf(float p) {
    unsigned long long u;
    asm("mov.b64 %0, {%1, %1};" : "=l"(u) : "f"(p));
    return u;
}
__device__ __forceinline__ unsigned long long pack2(float a, float b) {
    unsigned long long u;
    asm("mov.b64 %0, {%1, %2};" : "=l"(u) : "f"(a), "f"(b));
    return u;
}

// ------------------------------------------------------------------------------
// GEMM (f32x2 arm): used for QKV projection. 8 outs x 8 b per thread,
// software-pipelined LDG prefetch. grid (OUTS/256, KSPLIT), 128 threads.
// ------------------------------------------------------------------------------
__global__ __launch_bounds__(128)
void gemm_xwT(const float* __restrict__ x,
              const float* __restrict__ w0,
              const float* __restrict__ w1,
              const float* __restrict__ w2,
              int n0, int n1,
              float* __restrict__ yp, int OUTS)
{
    const int obase = blockIdx.x * 256;
    const float* wp;
    int orow;
    if (obase < n0)            { wp = w0; orow = obase; }
    else if (obase < n0 + n1)  { wp = w1; orow = obase - n0; }
    else                       { wp = w2; orow = obase - n0 - n1; }
    const int kb0 = blockIdx.y * KB;

    __shared__ __align__(16) float ws[16 * 264];   // [k][o:256 + pad]
    __shared__ __align__(16) float xs2[16 * 68];   // [k][b dup pairs]

    const int t    = threadIdx.x;
    const int lane = t & 31;
    const int w    = t >> 5;

    const int lxb = t >> 2;
    const int lxk = (t & 3) * 4;

    unsigned long long acc2[4][8];
#pragma unroll
    for (int p = 0; p < 4; p++)
#pragma unroll
        for (int i = 0; i < 8; i++) acc2[p][i] = 0ull;

    const int NT = KB / 16;

    float4 wv[8], xv;
#pragma unroll
    for (int h = 0; h < 2; h++)
#pragma unroll
        for (int q = 0; q < 4; q++)
            wv[h * 4 + q] = *(const float4*)&wp[(orow + t + h * 128) * 4096 + kb0 + q * 4];
    xv = *(const float4*)&x[lxb * 4096 + kb0 + lxk];

    for (int kt = 0; kt < NT; kt++) {
        __syncthreads();
#pragma unroll
        for (int h = 0; h < 2; h++) {
            const int o = t + h * 128;
#pragma unroll
            for (int q = 0; q < 4; q++) {
                ws[(q * 4 + 0) * 264 + o] = wv[h * 4 + q].x;
                ws[(q * 4 + 1) * 264 + o] = wv[h * 4 + q].y;
                ws[(q * 4 + 2) * 264 + o] = wv[h * 4 + q].z;
                ws[(q * 4 + 3) * 264 + o] = wv[h * 4 + q].w;
            }
        }
        xs2[(lxk + 0) * 68 + lxb * 2] = xv.x; xs2[(lxk + 0) * 68 + lxb * 2 + 1] = xv.x;
        xs2[(lxk + 1) * 68 + lxb * 2] = xv.y; xs2[(lxk + 1) * 68 + lxb * 2 + 1] = xv.y;
        xs2[(lxk + 2) * 68 + lxb * 2] = xv.z; xs2[(lxk + 2) * 68 + lxb * 2 + 1] = xv.z;
        xs2[(lxk + 3) * 68 + lxb * 2] = xv.w; xs2[(lxk + 3) * 68 + lxb * 2 + 1] = xv.w;
        __syncthreads();

        if (kt + 1 < NT) {
            const int kbase = kb0 + (kt + 1) * 16;
#pragma unroll
            for (int h = 0; h < 2; h++)
#pragma unroll
                for (int q = 0; q < 4; q++)
                    wv[h * 4 + q] = *(const float4*)&wp[(orow + t + h * 128) * 4096 + kbase + q * 4];
            xv = *(const float4*)&x[lxb * 4096 + kbase + lxk];
        }

#pragma unroll
        for (int kk = 0; kk < 16; kk++) {
            const ulonglong2 wA = *(const ulonglong2*)&ws[kk * 264 + lane * 4];
            const ulonglong2 wB = *(const ulonglong2*)&ws[kk * 264 + 128 + lane * 4];
#pragma unroll
            for (int i = 0; i < 8; i++) {
                const unsigned long long xp = *(const unsigned long long*)&xs2[kk * 68 + (w * 8 + i) * 2];
                acc2[0][i] = f2fma(wA.x, xp, acc2[0][i]);
                acc2[1][i] = f2fma(wA.y, xp, acc2[1][i]);
                acc2[2][i] = f2fma(wB.x, xp, acc2[2][i]);
                acc2[3][i] = f2fma(wB.y, xp, acc2[3][i]);
            }
        }
    }

#pragma unroll
    for (int p = 0; p < 4; p++) {
        const int o = obase + ((p < 2) ? 0 : 128) + lane * 4 + (p & 1) * 2;
#pragma unroll
        for (int i = 0; i < 8; i++) {
            const int b = w * 8 + i;
            float2 f = uf2(acc2[p][i]);
            *(float2*)&yp[(blockIdx.y * NB + b) * OUTS + o] = f;
        }
    }
}

// ------------------------------------------------------------------------------
// GEMM (scalar-FFMA arm): used for wo projection.
// grid (4096/256, KSPLIT), 256 threads. Thread tile 4 o x 8 b.
// Double-buffered smem, ONE __syncthreads per k-tile phase pair.
// ------------------------------------------------------------------------------
__global__ __launch_bounds__(256)
void gemm_xwT_s(const float* __restrict__ x,
                const float* __restrict__ w0,
                float* __restrict__ yp)
{
    const int obase = blockIdx.x * 256;
    const int kb0 = blockIdx.y * KB;

    __shared__ __align__(16) float ws[2 * 16 * 264];  // [buf][k][o]
    __shared__ __align__(16) float xs[2 * 16 * 36];   // [buf][k][b]

    const int t    = threadIdx.x;
    const int lane = t & 31;
    const int w    = t >> 5;

    const int og = (w & 1) * 128 + lane * 4;   // 4 outs
    const int bq = (w >> 1) * 8;               // 8 batches

    const int lxb = t >> 2;          // x load: batch (t<128)
    const int lxk = (t & 3) * 4;     // x load: k offset

    float acc[4][8];
#pragma unroll
    for (int j = 0; j < 4; j++)
#pragma unroll
        for (int i = 0; i < 8; i++) acc[j][i] = 0.f;

    const int NT = KB / 16;

    float4 wv[4], xv;
#pragma unroll
    for (int q = 0; q < 4; q++)
        wv[q] = *(const float4*)&w0[(obase + t) * 4096 + kb0 + q * 4];
    if (t < 128) xv = *(const float4*)&x[lxb * 4096 + kb0 + lxk];

    for (int kt = 0; kt < NT; kt++) {
        float* wsb = ws + (kt & 1) * (16 * 264);
        float* xsb = xs + (kt & 1) * (16 * 36);

#pragma unroll
        for (int q = 0; q < 4; q++) {
            wsb[(q * 4 + 0) * 264 + t] = wv[q].x;
            wsb[(q * 4 + 1) * 264 + t] = wv[q].y;
            wsb[(q * 4 + 2) * 264 + t] = wv[q].z;
            wsb[(q * 4 + 3) * 264 + t] = wv[q].w;
        }
        if (t < 128) {
            xsb[(lxk + 0) * 36 + lxb] = xv.x;
            xsb[(lxk + 1) * 36 + lxb] = xv.y;
            xsb[(lxk + 2) * 36 + lxb] = xv.z;
            xsb[(lxk + 3) * 36 + lxb] = xv.w;
        }
        __syncthreads();

        if (kt + 1 < NT) {
            const int kbase = kb0 + (kt + 1) * 16;
#pragma unroll
            for (int q = 0; q < 4; q++)
                wv[q] = *(const float4*)&w0[(obase + t) * 4096 + kbase + q * 4];
            if (t < 128) xv = *(const float4*)&x[lxb * 4096 + kbase + lxk];
        }

#pragma unroll
        for (int kk = 0; kk < 16; kk++) {
            const float4 w4 = *(const float4*)&wsb[kk * 264 + og];
            const float4 xA = *(const float4*)&xsb[kk * 36 + bq];
            const float4 xB = *(const float4*)&xsb[kk * 36 + bq + 4];
            acc[0][0] += w4.x * xA.x; acc[0][1] += w4.x * xA.y;
            acc[0][2] += w4.x * xA.z; acc[0][3] += w4.x * xA.w;
            acc[0][4] += w4.x * xB.x; acc[0][5] += w4.x * xB.y;
            acc[0][6] += w4.x * xB.z; acc[0][7] += w4.x * xB.w;
            acc[1][0] += w4.y * xA.x; acc[1][1] += w4.y * xA.y;
            acc[1][2] += w4.y * xA.z; acc[1][3] += w4.y * xA.w;
            acc[1][4] += w4.y * xB.x; acc[1][5] += w4.y * xB.y;
            acc[1][6] += w4.y * xB.z; acc[1][7] += w4.y * xB.w;
            acc[2][0] += w4.z * xA.x; acc[2][1] += w4.z * xA.y;
            acc[2][2] += w4.z * xA.z; acc[2][3] += w4.z * xA.w;
            acc[2][4] += w4.z * xB.x; acc[2][5] += w4.z * xB.y;
            acc[2][6] += w4.z * xB.z; acc[2][7] += w4.z * xB.w;
            acc[3][0] += w4.w * xA.x; acc[3][1] += w4.w * xA.y;
            acc[3][2] += w4.w * xA.z; acc[3][3] += w4.w * xA.w;
            acc[3][4] += w4.w * xB.x; acc[3][5] += w4.w * xB.y;
            acc[3][6] += w4.w * xB.z; acc[3][7] += w4.w * xB.w;
        }
        __syncthreads();
    }

#pragma unroll
    for (int i = 0; i < 8; i++) {
        const int b = bq + i;
        float4 o4 = make_float4(acc[0][i], acc[1][i], acc[2][i], acc[3][i]);
        *(float4*)&yp[(blockIdx.y * NB + b) * DIM + obase + og] = o4;
    }
}

// ------------------------------------------------------------------------------
// RoPE + k-split reduce. grid 384 x 256.
// ------------------------------------------------------------------------------
__global__ void rope_reduce(const float* __restrict__ qkvp,
                            const float* __restrict__ fc,
                            const float* __restrict__ fs,
                            float* __restrict__ qout,
                            float* __restrict__ kout,
                            float* __restrict__ vout)
{
    const int idx = blockIdx.x * 256 + threadIdx.x;  // < 98304
    const int b  = idx / 3072;
    const int jp = idx % 3072;
    const int j0 = jp * 2;

    float v0 = 0.f, v1 = 0.f;
#pragma unroll
    for (int s = 0; s < KSPLIT; s++) {
        const float* p = qkvp + (s * NB + b) * QKV_OUTS + j0;
        v0 += p[0];
        v1 += p[1];
    }
    if (j0 < DIM + KVD) {
        const int i = jp & 63;
        const float c = fc[i], s_ = fs[i];
        const float re = v0 * c - v1 * s_;
        const float im = v0 * s_ + v1 * c;
        v0 = re; v1 = im;
    }
    if (j0 < DIM) {
        qout[b * DIM + j0] = v0;
        qout[b * DIM + j0 + 1] = v1;
    } else if (j0 < DIM + KVD) {
        kout[b * KVD + (j0 - DIM)] = v0;
        kout[b * KVD + (j0 - DIM) + 1] = v1;
    } else {
        vout[b * KVD + (j0 - DIM - KVD)] = v0;
        vout[b * KVD + (j0 - DIM - KVD) + 1] = v1;
    }
}

// ------------------------------------------------------------------------------
// Flash-decode split attention v5: ONE barrier per tile (double-buffered part).
// Phase i: stage K(i) -> sync -> prefetch K(i+1) -> reduce part(i-1) -> QK(i).
// grid (256, 16), 256 threads, __ldcs streaming. smem ~48KB (4 CTA/SM).
// ------------------------------------------------------------------------------
__global__ __launch_bounds__(256, 4)
void attn_split(const float* __restrict__ q,
                const float* __restrict__ ck,
                const float* __restrict__ cv,
                float* __restrict__ pm,
                float* __restrict__ pl,
                float* __restrict__ pacc)
{
    const int bg = blockIdx.x;
    const int b = bg >> 3, g = bg & 7;
    const int split = blockIdx.y;
    const int t = threadIdx.x;
    const int lane = t & 31, w = t >> 5;
    const int sbase = split * SCHUNK;

    __shared__ __align__(16) float sm[12036];
    float* qs   = sm;              // [4][128]             512
    float* kbuf = sm + 512;        // 2 x [32][132]        8448  (aliased by pvp)
    float* sc   = sm + 8960;       // [4][256]             1024
    float* part = sm + 9984;       // 2 x [8][4][32]       2048
    float* mf   = sm + 12032;      // [4]
    float* pvp  = kbuf;            // alias, [8][4][128] = 4096

    const float scale = 0.08838834764831845f;  // 1/sqrt(128)

    // q staging (pre-scaled)
    for (int i = t; i < 512; i += 256) {
        const int r = i >> 7, d = i & 127;
        qs[r * 128 + d] = q[(b * HQ + g * NREP + r) * HD + d] * scale;
    }

    const int s_loc = t & 31;
    const int dg = t >> 5;
    const int base_d = dg * 16;
    const size_t ckb = (size_t)(b * MAXSEQ) * KVD + g * HD;

    float4 kreg[4];
#pragma unroll
    for (int i = 0; i < 4; i++) {
        const int f4 = t + i * 256;
        const int row = f4 >> 5, c4 = (f4 & 31) * 4;
        kreg[i] = __ldcs((const float4*)&ck[ckb + (size_t)(sbase + row) * KVD + c4]);
    }

    float mloc = -1e30f;

    for (int tile = 0; tile < SCHUNK / 32; tile++) {
        float* kb = kbuf + (tile & 1) * 4224;
        // stage K(tile)
#pragma unroll
        for (int i = 0; i < 4; i++) {
            const int f4 = t + i * 256;
            const int row = f4 >> 5, c4 = (f4 & 31) * 4;
            *(float4*)&kb[row * 132 + c4] = kreg[i];
        }
        __syncthreads();   // kb(tile) ready; part(tile-1) writes complete

        // prefetch K(tile+1)
        if (tile + 1 < SCHUNK / 32) {
#pragma unroll
            for (int i = 0; i < 4; i++) {
                const int f4 = t + i * 256;
                const int row = f4 >> 5, c4 = (f4 & 31) * 4;
                kreg[i] = __ldcs((const float4*)&ck[ckb + (size_t)(sbase + (tile + 1) * 32 + row) * KVD + c4]);
            }
        }

        // reduce part(tile-1) -> sc
        if (tile >= 1 && t < 128) {
            const float* pp = part + ((tile - 1) & 1) * 1024;
            const int r = t >> 5;
            float val = 0.f;
#pragma unroll
            for (int d8 = 0; d8 < 8; d8++) val += pp[(d8 * 4 + r) * 32 + lane];
            const int sg = sbase + (tile - 1) * 32 + lane;
            if (sg == NEWPOS) val = -1e30f;
            sc[r * SCHUNK + (tile - 1) * 32 + lane] = val;
            mloc = fmaxf(mloc, val);
        }

        // QK(tile) -> part(tile)
        unsigned long long racc[4] = {0ull, 0ull, 0ull, 0ull};
#pragma unroll
        for (int c = 0; c < 4; c++) {
            ulonglong2 kk = *(const ulonglong2*)&kb[s_loc * 132 + base_d + c * 4];
#pragma unroll
            for (int r = 0; r < 4; r++) {
                ulonglong2 qq = *(const ulonglong2*)&qs[r * 128 + base_d + c * 4];
                racc[r] = f2fma(kk.x, qq.x, racc[r]);
                racc[r] = f2fma(kk.y, qq.y, racc[r]);
            }
        }
        float* pw = part + (tile & 1) * 1024;
#pragma unroll
        for (int r = 0; r < 4; r++) {
            float2 f = uf2(racc[r]);
            pw[(dg * 4 + r) * 32 + s_loc] = f.x + f.y;
        }
    }
    __syncthreads();   // last tile's part writes complete

    // reduce final tile
    if (t < 128) {
        const int lt = SCHUNK / 32 - 1;
        const float* pp = part + (lt & 1) * 1024;
        const int r = t >> 5;
        float val = 0.f;
#pragma unroll
        for (int d8 = 0; d8 < 8; d8++) val += pp[(d8 * 4 + r) * 32 + lane];
        const int sg = sbase + lt * 32 + lane;
        if (sg == NEWPOS) val = -1e30f;
        sc[r * SCHUNK + lt * 32 + lane] = val;
        mloc = fmaxf(mloc, val);
    }

    // per-rep max
    if (t < 128) {
#pragma unroll
        for (int off = 16; off; off >>= 1)
            mloc = fmaxf(mloc, __shfl_xor_sync(0xffffffffu, mloc, off));
        if (lane == 0) mf[t >> 5] = mloc;
    }
    __syncthreads();

    // exp + row sums
    {
        const int r = t >> 6, s0 = t & 63;
        const float m = mf[r];
        float ls = 0.f;
#pragma unroll
        for (int j = 0; j < SCHUNK / 64; j++) {
            const int sl = s0 + j * 64;
            const float p = __expf(sc[r * SCHUNK + sl] - m);
            sc[r * SCHUNK + sl] = p;
            ls += p;
        }
#pragma unroll
        for (int off = 16; off; off >>= 1)
            ls += __shfl_xor_sync(0xffffffffu, ls, off);
        if (lane == 0) part[w] = ls;
    }
    __syncthreads();
    if (t < 4) {
        pm[bg * (NSPLIT * NREP) + split * NREP + t] = mf[t];
        pl[bg * (NSPLIT * NREP) + split * NREP + t] = part[2 * t] + part[2 * t + 1];
    }

    // P @ V : thread = (d-quarter, s-group of 32), loads unrolled x4, streaming
    {
        const int dq = lane;
        const int sg8 = w;
        const size_t cvb = (size_t)(b * MAXSEQ) * KVD + g * HD + dq * 4;
        unsigned long long a[4][2];
#pragma unroll
        for (int r = 0; r < 4; r++) { a[r][0] = 0ull; a[r][1] = 0ull; }
        for (int i0 = 0; i0 < 32; i0 += 4) {
            float4 vf[4];
#pragma unroll
            for (int j = 0; j < 4; j++) {
                const int sl = sg8 * 32 + i0 + j;
                vf[j] = __ldcs((const float4*)&cv[cvb + (size_t)(sbase + sl) * KVD]);
            }
#pragma unroll
            for (int j = 0; j < 4; j++) {
                const int sl = sg8 * 32 + i0 + j;
                const unsigned long long vx = pack2(vf[j].x, vf[j].y);
                const unsigned long long vy = pack2(vf[j].z, vf[j].w);
#pragma unroll
                for (int r = 0; r < 4; r++) {
                    const unsigned long long pp = dupf(sc[r * SCHUNK + sl]);
                    a[r][0] = f2fma(pp, vx, a[r][0]);
                    a[r][1] = f2fma(pp, vy, a[r][1]);
                }
            }
        }
#pragma unroll
        for (int r = 0; r < 4; r++) {
            float2 f0 = uf2(a[r][0]), f1 = uf2(a[r][1]);
            float4 o4 = make_float4(f0.x, f0.y, f1.x, f1.y);
            *(float4*)&pvp[(sg8 * 4 + r) * 128 + dq * 4] = o4;
        }
    }
    __syncthreads();
#pragma unroll
    for (int i = 0; i < 2; i++) {
        const int idx = t + i * 256;   // 512 outputs
        const int r = idx >> 7, d = idx & 127;
        float v = 0.f;
#pragma unroll
        for (int sgp = 0; sgp < 8; sgp++) v += pvp[(sgp * 4 + r) * 128 + d];
        pacc[((bg * NSPLIT + split) * NREP + r) * HD + d] = v;
    }
}

// ------------------------------------------------------------------------------
// Combine partials + new token (s=4095). grid (256, 4), 128 threads.
// ------------------------------------------------------------------------------
__global__ __launch_bounds__(128)
void attn_combine(const float* __restrict__ q,
                  const float* __restrict__ kn,
                  const float* __restrict__ vn,
                  const float* __restrict__ pm,
                  const float* __restrict__ pl,
                  const float* __restrict__ pacc,
                  float* __restrict__ attn)
{
    const int bg = blockIdx.x;
    const int b = bg >> 3, g = bg & 7;
    const int rr = blockIdx.y;
    const int t = threadIdx.x, lane = t & 31;
    __shared__ float sn1;
    const float scale = 0.08838834764831845f;

    if (t < 32) {
        const float4 k4 = *(const float4*)&kn[(b * HKV + g) * HD + lane * 4];
        const float4 q4 = *(const float4*)&q[(b * HQ + g * NREP + rr) * HD + lane * 4];
        float ds = k4.x * q4.x + k4.y * q4.y + k4.z * q4.z + k4.w * q4.w;
#pragma unroll
        for (int off = 16; off; off >>= 1) ds += __shfl_xor_sync(0xffffffffu, ds, off);
        if (lane == 0) sn1 = ds * scale;
    }
    __syncthreads();

    const int d = t;
    const float vnew = vn[(b * HKV + g) * HD + d];

    float mi[NSPLIT];
    float M = sn1;
#pragma unroll
    for (int i = 0; i < NSPLIT; i++) {
        mi[i] = pm[bg * (NSPLIT * NREP) + i * NREP + rr];
        M = fmaxf(M, mi[i]);
    }
    const float en = __expf(sn1 - M);
    float L = en;
    float num = en * vnew;
#pragma unroll
    for (int i = 0; i < NSPLIT; i++) {
        const float e = __expf(mi[i] - M);
        L += pl[bg * (NSPLIT * NREP) + i * NREP + rr] * e;
        num += pacc[((bg * NSPLIT + i) * NREP + rr) * HD + d] * e;
    }
    attn[(b * HQ + g * NREP + rr) * HD + d] = num / L;
}

// ------------------------------------------------------------------------------
// Final k-split reduce of wo GEMM partials -> d_out.  grid 512 x 256.
// ------------------------------------------------------------------------------
__global__ void final_reduce(const float* __restrict__ op, float* __restrict__ out)
{
    const int idx = blockIdx.x * 256 + threadIdx.x;  // < 131072
    float v = 0.f;
#pragma unroll
    for (int s = 0; s < KSPLIT; s++) v += op[s * NB * DIM + idx];
    out[idx] = v;
}

// ------------------------------------------------------------------------------
extern "C" void kernel_launch(void* const* d_in, const int* in_sizes, int n_in,
                              void* d_out, int out_size)
{
    const float* x  = (const float*)d_in[0];
    const float* ck = (const float*)d_in[1];
    const float* cv = (const float*)d_in[2];
    const float* wq = (const float*)d_in[3];
    const float* wk = (const float*)d_in[4];
    const float* wv = (const float*)d_in[5];
    const float* wo = (const float*)d_in[6];
    const float* fc = (const float*)d_in[7];
    const float* fs = (const float*)d_in[8];
    float* out = (float*)d_out;

    float *qkvp, *qb, *kn, *vn, *pm, *pl, *pacc, *attn, *op;
    cudaGetSymbolAddress((void**)&qkvp, g_qkvp);
    cudaGetSymbolAddress((void**)&qb,   g_q);
    cudaGetSymbolAddress((void**)&kn,   g_kn);
    cudaGetSymbolAddress((void**)&vn,   g_vn);
    cudaGetSymbolAddress((void**)&pm,   g_pm);
    cudaGetSymbolAddress((void**)&pl,   g_pl);
    cudaGetSymbolAddress((void**)&pacc, g_pacc);
    cudaGetSymbolAddress((void**)&attn, g_attn);
    cudaGetSymbolAddress((void**)&op,   g_op);

    // 1) fused QKV projection (f32x2, pipelined)
    gemm_xwT<<<dim3(QKV_OUTS / 256, KSPLIT), 128>>>(x, wq, wk, wv, DIM, KVD, qkvp, QKV_OUTS);
    // 2) reduce partials + RoPE
    rope_reduce<<<384, 256>>>(qkvp, fc, fs, qb, kn, vn);
    // 3) split attention over cached tokens (pos 4095 masked; 1 barrier/tile)
    attn_split<<<dim3(NB * HKV, NSPLIT), 256>>>(qb, ck, cv, pm, pl, pacc);
    // 4) combine + new token
    attn_combine<<<dim3(NB * HKV, NREP), 128>>>(qb, kn, vn, pm, pl, pacc, attn);
    // 5) output projection (scalar-FFMA)
    gemm_xwT_s<<<dim3(DIM / 256, KSPLIT), 256>>>(attn, wo, op);
    // 6) reduce to d_out
    final_reduce<<<512, 256>>>(op, out);
}